// round 2
// baseline (speedup 1.0000x reference)
#include <cuda_runtime.h>

// Problem constants
#define VOCAB 8192
#define NTOK  16384   // B*T = 8*2048
#define TI    128     // vocab columns per block tile
#define TJ    32      // W rows (output j) per block tile

// Scratch (__device__ globals — no allocation allowed)
__device__ int   g_counts[VOCAB];
__device__ int   g_offsets[VOCAB + 1];
__device__ int   g_cursor[VOCAB];
__device__ int   g_list[NTOK];       // packed (vocab << 16) | token
__device__ float g_sumexp[NTOK];
__device__ float g_nll[NTOK];

// ---------------------------------------------------------------------------
__global__ void k_init() {
    int i = blockIdx.x * blockDim.x + threadIdx.x;
    if (i < VOCAB) g_counts[i] = 0;
    if (i < NTOK)  g_sumexp[i] = 0.0f;
}

__global__ void k_hist(const int* __restrict__ idx) {
    int t = blockIdx.x * blockDim.x + threadIdx.x;
    if (t < NTOK) atomicAdd(&g_counts[idx[t]], 1);
}

// Exclusive prefix sum over 8192 counts, single block of 1024 threads.
__global__ void k_scan() {
    __shared__ int part[1024];
    int tid = threadIdx.x;
    int base = tid * 8;
    int loc[8];
    int s = 0;
#pragma unroll
    for (int k = 0; k < 8; k++) { loc[k] = s; s += g_counts[base + k]; }
    part[tid] = s;
    __syncthreads();
    // Hillis-Steele inclusive scan
    for (int off = 1; off < 1024; off <<= 1) {
        int v = (tid >= off) ? part[tid - off] : 0;
        __syncthreads();
        part[tid] += v;
        __syncthreads();
    }
    int pre = (tid == 0) ? 0 : part[tid - 1];
#pragma unroll
    for (int k = 0; k < 8; k++) {
        int o = pre + loc[k];
        g_offsets[base + k] = o;
        g_cursor[base + k]  = o;
    }
    if (tid == 1023) g_offsets[VOCAB] = part[1023];
}

__global__ void k_scatter(const int* __restrict__ idx) {
    int t = blockIdx.x * blockDim.x + threadIdx.x;
    if (t < NTOK) {
        int v = idx[t];
        int pos = atomicAdd(&g_cursor[v], 1);
        g_list[pos] = (v << 16) | t;
    }
}

// ---------------------------------------------------------------------------
// Main kernel: grid (VOCAB/TI = 64, VOCAB/TJ = 256), 256 threads.
// Loads W[j0:j0+32, i0:i0+128] coalesced, stages transposed access via smem,
// writes 128B-contiguous chunks of each output row + accumulates sum(exp).
__global__ __launch_bounds__(256)
void k_main(const float* __restrict__ W, const float* __restrict__ bias,
            float* __restrict__ out) {
    __shared__ float sm[TJ][TI + 1];   // [32][129] — conflict-free both ways

    const int i0  = blockIdx.x * TI;
    const int j0  = blockIdx.y * TJ;
    const int tid = threadIdx.x;

    // Load phase: 32 rows x 128 cols, scalar loads, lanes along contiguous i.
    const int ii    = tid & 127;
    const int jbase = tid >> 7;       // 0 or 1
#pragma unroll
    for (int k = 0; k < 16; k++) {
        int jj = jbase + k * 2;
        sm[jj][ii] = W[(size_t)(j0 + jj) * VOCAB + i0 + ii];
    }

    const int lane = tid & 31;
    const int wid  = tid >> 5;
    const float bj = bias[j0 + lane];

    const int segs = g_offsets[i0];
    const int sege = g_offsets[i0 + TI];
    __syncthreads();

    for (int k = segs + wid; k < sege; k += 8) {
        int e  = g_list[k];
        int t  = e & 0xFFFF;
        int di = (e >> 16) - i0;
        float v = sm[lane][di] + bj;           // conflict-free column read
        out[(size_t)t * VOCAB + j0 + lane] = v; // coalesced 128B store
        float ex = __expf(v);
#pragma unroll
        for (int o = 16; o > 0; o >>= 1)
            ex += __shfl_xor_sync(0xffffffffu, ex, o);
        if (lane == 0) atomicAdd(&g_sumexp[t], ex);
    }
}

// ---------------------------------------------------------------------------
__global__ void k_nll(const int* __restrict__ idx, const int* __restrict__ tgt,
                      const float* __restrict__ W, const float* __restrict__ bias) {
    int t = blockIdx.x * blockDim.x + threadIdx.x;
    if (t < NTOK) {
        int tg = tgt[t];
        float nll = 0.0f;
        if (tg >= 0) {
            float lt = W[(size_t)tg * VOCAB + idx[t]] + bias[tg];
            nll = logf(g_sumexp[t]) - lt;
        }
        g_nll[t] = nll;
    }
}

__global__ void k_reduce(const int* __restrict__ tgt, float* __restrict__ out,
                         int loss_index) {
    __shared__ float ssum[256];
    __shared__ float scnt[256];
    int tid = threadIdx.x;
    float s = 0.0f, c = 0.0f;
    for (int t = tid; t < NTOK; t += 256) {
        s += g_nll[t];
        c += (tgt[t] != -1) ? 1.0f : 0.0f;
    }
    ssum[tid] = s; scnt[tid] = c;
    __syncthreads();
    for (int o = 128; o > 0; o >>= 1) {
        if (tid < o) { ssum[tid] += ssum[tid + o]; scnt[tid] += scnt[tid + o]; }
        __syncthreads();
    }
    if (tid == 0) out[loss_index] = ssum[0] / fmaxf(scnt[0], 1.0f);
}

// ---------------------------------------------------------------------------
extern "C" void kernel_launch(void* const* d_in, const int* in_sizes, int n_in,
                              void* d_out, int out_size) {
    const int*   idx  = (const int*)d_in[0];
    const int*   tgt  = (const int*)d_in[1];
    const float* W    = (const float*)d_in[2];
    const float* bias = (const float*)d_in[3];
    float*       out  = (float*)d_out;

    k_init<<<(NTOK + 255) / 256, 256>>>();
    k_hist<<<NTOK / 256, 256>>>(idx);
    k_scan<<<1, 1024>>>();
    k_scatter<<<NTOK / 256, 256>>>(idx);
    k_main<<<dim3(VOCAB / TI, VOCAB / TJ), 256>>>(W, bias, out);
    k_nll<<<NTOK / 256, 256>>>(idx, tgt, W, bias);
    k_reduce<<<1, 256>>>(tgt, out, out_size - 1);
}

// round 3
// speedup vs baseline: 1.3041x; 1.3041x over previous
#include <cuda_runtime.h>

// Problem constants
#define VOCAB 8192
#define NTOK  16384   // B*T = 8*2048
#define TI    128     // vocab columns per block tile
#define TJ    64      // W rows (output j) per block tile
#define NJB   (VOCAB / TJ)   // 128 j-blocks

// Scratch (__device__ globals — no allocation allowed)
__device__ int   g_counts[VOCAB];
__device__ int   g_offsets[VOCAB + 1];
__device__ int   g_cursor[VOCAB];
__device__ int   g_list[NTOK];              // packed (vocab << 16) | token
__device__ float g_partial[NJB * VOCAB];    // per-jblock column partial sums of exp
__device__ float g_S[VOCAB];                // S[i] = sum_j exp(W[j,i]+b[j])
__device__ float g_nll[NTOK];

// ---------------------------------------------------------------------------
__global__ void k_init() {
    int i = blockIdx.x * blockDim.x + threadIdx.x;
    if (i < VOCAB) g_counts[i] = 0;
}

__global__ void k_hist(const int* __restrict__ idx) {
    int t = blockIdx.x * blockDim.x + threadIdx.x;
    if (t < NTOK) atomicAdd(&g_counts[idx[t]], 1);
}

// Exclusive prefix sum over 8192 counts, single block of 1024 threads.
__global__ void k_scan() {
    __shared__ int part[1024];
    int tid = threadIdx.x;
    int base = tid * 8;
    int loc[8];
    int s = 0;
#pragma unroll
    for (int k = 0; k < 8; k++) { loc[k] = s; s += g_counts[base + k]; }
    part[tid] = s;
    __syncthreads();
    for (int off = 1; off < 1024; off <<= 1) {
        int v = (tid >= off) ? part[tid - off] : 0;
        __syncthreads();
        part[tid] += v;
        __syncthreads();
    }
    int pre = (tid == 0) ? 0 : part[tid - 1];
#pragma unroll
    for (int k = 0; k < 8; k++) {
        int o = pre + loc[k];
        g_offsets[base + k] = o;
        g_cursor[base + k]  = o;
    }
    if (tid == 1023) g_offsets[VOCAB] = part[1023];
}

__global__ void k_scatter(const int* __restrict__ idx) {
    int t = blockIdx.x * blockDim.x + threadIdx.x;
    if (t < NTOK) {
        int v = idx[t];
        int pos = atomicAdd(&g_cursor[v], 1);
        g_list[pos] = (v << 16) | t;
    }
}

// ---------------------------------------------------------------------------
// Main kernel: grid (VOCAB/TI = 64, VOCAB/TJ = 128), 256 threads.
// Load phase: stages W[j0:j0+64, i0:i0+128] into smem (coalesced along i),
//   fusing exp(W+b) column-partial accumulation (each W element exp'd once).
// Token phase: pure smem-read + bias-add + coalesced streaming store.
__global__ __launch_bounds__(256)
void k_main(const float* __restrict__ W, const float* __restrict__ bias,
            float* __restrict__ out) {
    __shared__ float sm[TJ][TI + 1];   // [64][129] — conflict-free both ways
    __shared__ float sbias[TJ];
    __shared__ float pacc[256];

    const int i0  = blockIdx.x * TI;
    const int j0  = blockIdx.y * TJ;
    const int tid = threadIdx.x;

    if (tid < TJ) sbias[tid] = bias[j0 + tid];
    __syncthreads();

    // Load + exp-accumulate: lanes along contiguous i; 2 threads per column.
    const int ii    = tid & 127;
    const int jbase = tid >> 7;        // 0 or 1
    float acc = 0.0f;
#pragma unroll
    for (int k = 0; k < TJ / 2; k++) {
        int jj = jbase + k * 2;
        float w = __ldcs(&W[(size_t)(j0 + jj) * VOCAB + i0 + ii]);
        sm[jj][ii] = w;
        acc += __expf(w + sbias[jj]);
    }
    pacc[tid] = acc;

    const int lane = tid & 31;
    const int wid  = tid >> 5;
    const float bj0 = sbias[lane];
    const float bj1 = sbias[lane + 32];

    const int segs = g_offsets[i0];
    const int sege = g_offsets[i0 + TI];
    __syncthreads();

    // Per-column exp partials -> global partial buffer (no atomics).
    if (tid < TI)
        g_partial[(size_t)blockIdx.y * VOCAB + i0 + tid] = pacc[tid] + pacc[tid + 128];

    // Token loop: one warp per token per iteration.
    for (int k = segs + wid; k < sege; k += 8) {
        int e  = g_list[k];
        int t  = e & 0xFFFF;
        int di = (e >> 16) - i0;
        float v0 = sm[lane][di]      + bj0;   // conflict-free column reads
        float v1 = sm[lane + 32][di] + bj1;
        size_t o = (size_t)t * VOCAB + j0;
        __stcs(&out[o + lane], v0);           // coalesced 128B streaming stores
        __stcs(&out[o + 32 + lane], v1);
    }
}

// ---------------------------------------------------------------------------
// Reduce partials: S[i] = sum over 128 j-blocks.
__global__ void k_sumS() {
    int i = blockIdx.x * blockDim.x + threadIdx.x;  // 0..VOCAB-1
    float s = 0.0f;
#pragma unroll 8
    for (int jb = 0; jb < NJB; jb++)
        s += g_partial[(size_t)jb * VOCAB + i];
    g_S[i] = s;
}

__global__ void k_nll(const int* __restrict__ idx, const int* __restrict__ tgt,
                      const float* __restrict__ W, const float* __restrict__ bias) {
    int t = blockIdx.x * blockDim.x + threadIdx.x;
    if (t < NTOK) {
        int tg = tgt[t];
        float nll = 0.0f;
        if (tg >= 0) {
            float lt = W[(size_t)tg * VOCAB + idx[t]] + bias[tg];
            nll = logf(g_S[idx[t]]) - lt;
        }
        g_nll[t] = nll;
    }
}

__global__ void k_reduce(const int* __restrict__ tgt, float* __restrict__ out,
                         int loss_index) {
    __shared__ float ssum[256];
    __shared__ float scnt[256];
    int tid = threadIdx.x;
    float s = 0.0f, c = 0.0f;
    for (int t = tid; t < NTOK; t += 256) {
        s += g_nll[t];
        c += (tgt[t] != -1) ? 1.0f : 0.0f;
    }
    ssum[tid] = s; scnt[tid] = c;
    __syncthreads();
    for (int o = 128; o > 0; o >>= 1) {
        if (tid < o) { ssum[tid] += ssum[tid + o]; scnt[tid] += scnt[tid + o]; }
        __syncthreads();
    }
    if (tid == 0) out[loss_index] = ssum[0] / fmaxf(scnt[0], 1.0f);
}

// ---------------------------------------------------------------------------
extern "C" void kernel_launch(void* const* d_in, const int* in_sizes, int n_in,
                              void* d_out, int out_size) {
    const int*   idx  = (const int*)d_in[0];
    const int*   tgt  = (const int*)d_in[1];
    const float* W    = (const float*)d_in[2];
    const float* bias = (const float*)d_in[3];
    float*       out  = (float*)d_out;

    k_init<<<VOCAB / 256, 256>>>();
    k_hist<<<NTOK / 256, 256>>>(idx);
    k_scan<<<1, 1024>>>();
    k_scatter<<<NTOK / 256, 256>>>(idx);
    k_main<<<dim3(VOCAB / TI, VOCAB / TJ), 256>>>(W, bias, out);
    k_sumS<<<VOCAB / 256, 256>>>();
    k_nll<<<NTOK / 256, 256>>>(idx, tgt, W, bias);
    k_reduce<<<1, 256>>>(tgt, out, out_size - 1);
}

// round 5
// speedup vs baseline: 1.3339x; 1.0229x over previous
#include <cuda_runtime.h>

// Problem constants
#define VOCAB  8192
#define NTOK   16384          // B*T = 8*2048
#define TI     128            // vocab columns per i-tile (64 tiles)
#define TJ     128            // output j per block tile  (64 tiles)
#define NIB    (VOCAB / TI)   // 64 i-tiles (= segment bins)
#define NJB    (VOCAB / TJ)   // 64 j-blocks
#define SEGCAP NTOK           // worst-case tokens per bin (adversarial-safe)
#define SMSTRIDE 132          // smT row stride in floats: 132/4=33 odd -> cf STS/LDS.128

// Scratch (__device__ globals — zero-initialized at module load; no allocation)
__device__ int   g_cnt[NIB];                 // per-bin token counts (reset by k_reduce)
__device__ int   g_list[NIB * SEGCAP];       // packed (vocab << 16) | token
__device__ float g_partial[NJB * VOCAB];     // per-jblock column partials of sum(exp)
__device__ float g_S[VOCAB];                 // S[i] = sum_j exp(W[j,i]+b[j])
__device__ float g_nll[NTOK];

// ---------------------------------------------------------------------------
// Scatter tokens into per-i-tile segments (smem-aggregated atomics).
__global__ __launch_bounds__(256)
void k_scatter(const int* __restrict__ idx) {
    __shared__ int lcnt[NIB];
    __shared__ int lbase[NIB];
    int tid = threadIdx.x;
    if (tid < NIB) lcnt[tid] = 0;
    __syncthreads();
    int t = blockIdx.x * 256 + tid;
    int v = idx[t];
    int bin = v >> 7;
    int lp = atomicAdd(&lcnt[bin], 1);
    __syncthreads();
    if (tid < NIB && lcnt[tid] > 0)
        lbase[tid] = atomicAdd(&g_cnt[tid], lcnt[tid]);
    __syncthreads();
    g_list[bin * SEGCAP + lbase[bin] + lp] = (v << 16) | t;
}

// ---------------------------------------------------------------------------
// Main kernel: grid (64 i-tiles, 64 j-tiles), 256 threads.
// Load phase: warp-transposed load of W tile (+bias) into smT[i][j] with
//   fused exp() column-partial accumulation (each W element exp'd once).
// Token phase: 1 broadcast LDG + 1 LDS.128 + 1 STG.128 per token.
__global__ __launch_bounds__(256, 3)
void k_main(const float* __restrict__ W, const float* __restrict__ bias,
            float* __restrict__ out) {
    __shared__ float smT[TI * SMSTRIDE];   // [128][132] transposed: smT[i][j]
    __shared__ float sbias[TJ];
    __shared__ float psum[8][32];

    const int i0   = blockIdx.x * TI;
    const int j0   = blockIdx.y * TJ;
    const int tid  = threadIdx.x;
    const int lane = tid & 31;
    const int wid  = tid >> 5;

    if (tid < TJ) sbias[tid] = bias[j0 + tid];
    __syncthreads();

    // Each warp owns i-group (wid&3) and j-groups {wid>>2, (wid>>2)+2} (32x32 subtiles).
    const int ii0 = (wid & 3) * 32;
    float acc = 0.0f;

#pragma unroll
    for (int s = 0; s < 2; s++) {
        const int jj0 = ((wid >> 2) + 2 * s) * 32;
        float v[32];
        // 32 coalesced scalar loads: lane ends up holding a j-contiguous column.
#pragma unroll
        for (int r = 0; r < 32; r++)
            v[r] = __ldcs(&W[(size_t)(j0 + jj0 + r) * VOCAB + i0 + ii0 + lane]);
#pragma unroll
        for (int r = 0; r < 32; r++) {
            v[r] += sbias[jj0 + r];
            acc += __expf(v[r]);
        }
        // 8 conflict-free STS.128 into transposed layout.
        float* row = &smT[(ii0 + lane) * SMSTRIDE + jj0];
#pragma unroll
        for (int c = 0; c < 8; c++)
            reinterpret_cast<float4*>(row)[c] =
                make_float4(v[4 * c], v[4 * c + 1], v[4 * c + 2], v[4 * c + 3]);
    }
    psum[wid][lane] = acc;

    const int bi  = blockIdx.x;
    const int cnt = g_cnt[bi];
    __syncthreads();

    // Column exp-partials -> global (no atomics).
    if (tid < TI) {
        int g = tid >> 5, l = tid & 31;
        g_partial[(size_t)blockIdx.y * VOCAB + i0 + tid] =
            psum[g][l] + psum[g + 4][l];
    }

    // Token loop: one warp per token per iteration; 512B coalesced store.
    const int base = bi * SEGCAP;
    for (int k = wid; k < cnt; k += 8) {
        int e  = g_list[base + k];              // uniform across warp
        int t  = e & 0xFFFF;
        int di = (e >> 16) - i0;
        float4 v4 = *reinterpret_cast<const float4*>(&smT[di * SMSTRIDE + 4 * lane]);
        __stcs(reinterpret_cast<float4*>(out + (size_t)t * VOCAB + j0) + lane, v4);
    }
}

// ---------------------------------------------------------------------------
__global__ void k_sumS() {
    int i = blockIdx.x * blockDim.x + threadIdx.x;
    float s = 0.0f;
#pragma unroll 8
    for (int jb = 0; jb < NJB; jb++)
        s += g_partial[(size_t)jb * VOCAB + i];
    g_S[i] = s;
}

__global__ void k_nll(const int* __restrict__ idx, const int* __restrict__ tgt,
                      const float* __restrict__ W, const float* __restrict__ bias) {
    int t = blockIdx.x * blockDim.x + threadIdx.x;
    if (t < NTOK) {
        int tg = tgt[t];
        float nll = 0.0f;
        if (tg >= 0) {
            float lt = W[(size_t)tg * VOCAB + idx[t]] + bias[tg];
            nll = logf(g_S[idx[t]]) - lt;
        }
        g_nll[t] = nll;
    }
}

__global__ void k_reduce(const int* __restrict__ tgt, float* __restrict__ out,
                         int loss_index) {
    __shared__ float ssum[256];
    __shared__ float scnt[256];
    int tid = threadIdx.x;
    float s = 0.0f, c = 0.0f;
    for (int t = tid; t < NTOK; t += 256) {
        s += g_nll[t];
        c += (tgt[t] != -1) ? 1.0f : 0.0f;
    }
    ssum[tid] = s; scnt[tid] = c;
    __syncthreads();
    for (int o = 128; o > 0; o >>= 1) {
        if (tid < o) { ssum[tid] += ssum[tid + o]; scnt[tid] += scnt[tid + o]; }
        __syncthreads();
    }
    if (tid == 0) out[loss_index] = ssum[0] / fmaxf(scnt[0], 1.0f);
    // Reset bin counters for the next graph replay.
    if (tid < NIB) g_cnt[tid] = 0;
}

// ---------------------------------------------------------------------------
extern "C" void kernel_launch(void* const* d_in, const int* in_sizes, int n_in,
                              void* d_out, int out_size) {
    const int*   idx  = (const int*)d_in[0];
    const int*   tgt  = (const int*)d_in[1];
    const float* W    = (const float*)d_in[2];
    const float* bias = (const float*)d_in[3];
    float*       out  = (float*)d_out;

    k_scatter<<<NTOK / 256, 256>>>(idx);
    k_main<<<dim3(NIB, NJB), 256>>>(W, bias, out);
    k_sumS<<<VOCAB / 256, 256>>>();
    k_nll<<<NTOK / 256, 256>>>(idx, tgt, W, bias);
    k_reduce<<<1, 256>>>(tgt, out, out_size - 1);
}

// round 6
// speedup vs baseline: 1.4090x; 1.0563x over previous
#include <cuda_runtime.h>

// Problem constants
#define VOCAB  8192
#define NTOK   16384          // B*T = 8*2048
#define TI     128            // vocab columns per i-tile (64 tiles)
#define TJ     128            // output j per block tile  (64 tiles)
#define NIB    (VOCAB / TI)   // 64 i-tiles (= segment bins)
#define NJB    (VOCAB / TJ)   // 64 j-blocks
#define SEGCAP NTOK           // worst-case tokens per bin (adversarial-safe)
#define LCAP   1024           // smem-staged list capacity (mean 256, sigma 16)
#define SMSTRIDE 132          // smT row stride in floats: 33 float4 -> conflict-free

// Scratch (__device__ globals — zero-initialized at module load; no allocation)
__device__ int   g_cnt[NIB];                 // per-bin token counts (reset by k_reduce)
__device__ int   g_list[NIB * SEGCAP];       // packed (vocab << 16) | token
__device__ float g_partial[NJB * VOCAB];     // per-jblock column partials of sum(exp)
__device__ float g_S[VOCAB];                 // S[i] = sum_j exp(W[j,i]+b[j])
__device__ float g_nll[NTOK];

// ---------------------------------------------------------------------------
// Scatter tokens into per-i-tile segments (smem-aggregated atomics).
__global__ __launch_bounds__(256)
void k_scatter(const int* __restrict__ idx) {
    __shared__ int lcnt[NIB];
    __shared__ int lbase[NIB];
    int tid = threadIdx.x;
    if (tid < NIB) lcnt[tid] = 0;
    __syncthreads();
    int t = blockIdx.x * 256 + tid;
    int v = idx[t];
    int bin = v >> 7;
    int lp = atomicAdd(&lcnt[bin], 1);
    __syncthreads();
    if (tid < NIB && lcnt[tid] > 0)
        lbase[tid] = atomicAdd(&g_cnt[tid], lcnt[tid]);
    __syncthreads();
    g_list[bin * SEGCAP + lbase[bin] + lp] = (v << 16) | t;
}

// Padding kernel: aligns k_main to global launch #6 so ncu (-s 5 -c 1)
// finally profiles the main kernel instead of a setup kernel.
__global__ void k_pad() {}

// ---------------------------------------------------------------------------
// Main kernel: grid (64 i-tiles, 64 j-tiles), 256 threads.
// Load phase: stage token list into smem + warp-transposed load of W tile
//   (+bias) into smT[i][j], fused exp() column-partial accumulation.
// Token phase: 4-way batched, all-smem addressing, independent LDS/STG.
__global__ __launch_bounds__(256, 3)
void k_main(const float* __restrict__ W, const float* __restrict__ bias,
            float* __restrict__ out) {
    __shared__ float smT[TI * SMSTRIDE];   // [128][132] transposed: smT[i][j]
    __shared__ float sbias[TJ];
    __shared__ float psum[8][32];
    __shared__ int   slist[LCAP];

    const int i0   = blockIdx.x * TI;
    const int j0   = blockIdx.y * TJ;
    const int tid  = threadIdx.x;
    const int lane = tid & 31;
    const int wid  = tid >> 5;
    const int bi   = blockIdx.x;
    const int base = bi * SEGCAP;
    const int cnt  = g_cnt[bi];

    // Stage token list (coalesced, overlaps with W loads below).
    const int scnt = cnt < LCAP ? cnt : LCAP;
    for (int k = tid; k < scnt; k += 256) slist[k] = g_list[base + k];

    if (tid < TJ) sbias[tid] = bias[j0 + tid];
    __syncthreads();   // sbias ready (W-load needs it)

    // Each warp owns i-group (wid&3) and j-groups {wid>>2, (wid>>2)+2}.
    const int ii0 = (wid & 3) * 32;
    float acc = 0.0f;

#pragma unroll
    for (int s = 0; s < 2; s++) {
        const int jj0 = ((wid >> 2) + 2 * s) * 32;
        float v[32];
#pragma unroll
        for (int r = 0; r < 32; r++)
            v[r] = __ldcs(&W[(size_t)(j0 + jj0 + r) * VOCAB + i0 + ii0 + lane]);
#pragma unroll
        for (int r = 0; r < 32; r++) {
            v[r] += sbias[jj0 + r];
            acc += __expf(v[r]);
        }
        float* row = &smT[(ii0 + lane) * SMSTRIDE + jj0];
#pragma unroll
        for (int c = 0; c < 8; c++)
            reinterpret_cast<float4*>(row)[c] =
                make_float4(v[4 * c], v[4 * c + 1], v[4 * c + 2], v[4 * c + 3]);
    }
    psum[wid][lane] = acc;
    __syncthreads();

    // Column exp-partials -> global (no atomics).
    if (tid < TI) {
        int g = tid >> 5, l = tid & 31;
        g_partial[(size_t)blockIdx.y * VOCAB + i0 + tid] =
            psum[g][l] + psum[g + 4][l];
    }

    // Token loop: contiguous per-warp chunk, 4-way batched for MLP.
    const int per = (cnt + 7) >> 3;
    int k        = wid * per;
    const int ke = min(k + per, cnt);

    for (; k + 4 <= ke; k += 4) {
        int e0 = (k     < LCAP) ? slist[k]     : g_list[base + k];
        int e1 = (k + 1 < LCAP) ? slist[k + 1] : g_list[base + k + 1];
        int e2 = (k + 2 < LCAP) ? slist[k + 2] : g_list[base + k + 2];
        int e3 = (k + 3 < LCAP) ? slist[k + 3] : g_list[base + k + 3];
        float4 a0 = *reinterpret_cast<const float4*>(&smT[((e0 >> 16) - i0) * SMSTRIDE + 4 * lane]);
        float4 a1 = *reinterpret_cast<const float4*>(&smT[((e1 >> 16) - i0) * SMSTRIDE + 4 * lane]);
        float4 a2 = *reinterpret_cast<const float4*>(&smT[((e2 >> 16) - i0) * SMSTRIDE + 4 * lane]);
        float4 a3 = *reinterpret_cast<const float4*>(&smT[((e3 >> 16) - i0) * SMSTRIDE + 4 * lane]);
        __stcs(reinterpret_cast<float4*>(out + (size_t)(e0 & 0xFFFF) * VOCAB + j0) + lane, a0);
        __stcs(reinterpret_cast<float4*>(out + (size_t)(e1 & 0xFFFF) * VOCAB + j0) + lane, a1);
        __stcs(reinterpret_cast<float4*>(out + (size_t)(e2 & 0xFFFF) * VOCAB + j0) + lane, a2);
        __stcs(reinterpret_cast<float4*>(out + (size_t)(e3 & 0xFFFF) * VOCAB + j0) + lane, a3);
    }
    for (; k < ke; k++) {
        int e = (k < LCAP) ? slist[k] : g_list[base + k];
        float4 a = *reinterpret_cast<const float4*>(&smT[((e >> 16) - i0) * SMSTRIDE + 4 * lane]);
        __stcs(reinterpret_cast<float4*>(out + (size_t)(e & 0xFFFF) * VOCAB + j0) + lane, a);
    }
}

// ---------------------------------------------------------------------------
__global__ void k_sumS() {
    int i = blockIdx.x * blockDim.x + threadIdx.x;
    float s = 0.0f;
#pragma unroll 8
    for (int jb = 0; jb < NJB; jb++)
        s += g_partial[(size_t)jb * VOCAB + i];
    g_S[i] = s;
}

__global__ void k_nll(const int* __restrict__ idx, const int* __restrict__ tgt,
                      const float* __restrict__ W, const float* __restrict__ bias) {
    int t = blockIdx.x * blockDim.x + threadIdx.x;
    if (t < NTOK) {
        int tg = tgt[t];
        float nll = 0.0f;
        if (tg >= 0) {
            float lt = W[(size_t)tg * VOCAB + idx[t]] + bias[tg];
            nll = logf(g_S[idx[t]]) - lt;
        }
        g_nll[t] = nll;
    }
}

__global__ void k_reduce(const int* __restrict__ tgt, float* __restrict__ out,
                         int loss_index) {
    __shared__ float ssum[256];
    __shared__ float scnt[256];
    int tid = threadIdx.x;
    float s = 0.0f, c = 0.0f;
    for (int t = tid; t < NTOK; t += 256) {
        s += g_nll[t];
        c += (tgt[t] != -1) ? 1.0f : 0.0f;
    }
    ssum[tid] = s; scnt[tid] = c;
    __syncthreads();
    for (int o = 128; o > 0; o >>= 1) {
        if (tid < o) { ssum[tid] += ssum[tid + o]; scnt[tid] += scnt[tid + o]; }
        __syncthreads();
    }
    if (tid == 0) out[loss_index] = ssum[0] / fmaxf(scnt[0], 1.0f);
    // Reset bin counters for the next graph replay.
    if (tid < NIB) g_cnt[tid] = 0;
}

// ---------------------------------------------------------------------------
extern "C" void kernel_launch(void* const* d_in, const int* in_sizes, int n_in,
                              void* d_out, int out_size) {
    const int*   idx  = (const int*)d_in[0];
    const int*   tgt  = (const int*)d_in[1];
    const float* W    = (const float*)d_in[2];
    const float* bias = (const float*)d_in[3];
    float*       out  = (float*)d_out;

    k_scatter<<<NTOK / 256, 256>>>(idx);   // launch 1
    k_pad<<<1, 32>>>();                    // launch 2
    k_pad<<<1, 32>>>();                    // launch 3
    k_pad<<<1, 32>>>();                    // launch 4
    k_pad<<<1, 32>>>();                    // launch 5
    k_main<<<dim3(NIB, NJB), 256>>>(W, bias, out);   // launch 6 -> ncu target
    k_sumS<<<VOCAB / 256, 256>>>();
    k_nll<<<NTOK / 256, 256>>>(idx, tgt, W, bias);
    k_reduce<<<1, 256>>>(tgt, out, out_size - 1);
}

// round 8
// speedup vs baseline: 1.5004x; 1.0649x over previous
#include <cuda_runtime.h>
#include <cstdint>

// Problem constants
#define VOCAB  8192
#define NTOK   16384          // B*T = 8*2048
#define TI     128            // vocab columns per i-tile (64 tiles)
#define TJ     128            // output j per block tile  (64 tiles)
#define NIB    (VOCAB / TI)   // 64 i-tiles (= segment bins)
#define NJB    (VOCAB / TJ)   // 64 j-blocks
#define SEGCAP NTOK           // worst-case tokens per bin (adversarial-safe)
#define LCAP   1024           // smem-staged list capacity (mean 256, sigma 16)
#define SMSTRIDE 132          // smT row stride in floats: 132*4=528B (16B multiple)

// Scratch (__device__ globals — zero-initialized at module load; no allocation)
__device__ int   g_cnt[NIB];                 // per-bin token counts (reset by k_reduce)
__device__ int   g_list[NIB * SEGCAP];       // packed (vocab << 16) | token
__device__ float g_partial[NJB * VOCAB];     // per-jblock column partials of sum(exp)
__device__ float g_S[VOCAB];                 // S[i] = sum_j exp(W[j,i]+b[j])
__device__ float g_nll[NTOK];

// ---------------------------------------------------------------------------
// Scatter tokens into per-i-tile segments (smem-aggregated atomics).
__global__ __launch_bounds__(256)
void k_scatter(const int* __restrict__ idx) {
    __shared__ int lcnt[NIB];
    __shared__ int lbase[NIB];
    int tid = threadIdx.x;
    if (tid < NIB) lcnt[tid] = 0;
    __syncthreads();
    int t = blockIdx.x * 256 + tid;
    int v = idx[t];
    int bin = v >> 7;
    int lp = atomicAdd(&lcnt[bin], 1);
    __syncthreads();
    if (tid < NIB && lcnt[tid] > 0)
        lbase[tid] = atomicAdd(&g_cnt[tid], lcnt[tid]);
    __syncthreads();
    g_list[bin * SEGCAP + lbase[bin] + lp] = (v << 16) | t;
}

// Padding kernel: the profiler captures the 4th launch; two pads put k_main there.
__global__ void k_pad() {}

// ---------------------------------------------------------------------------
// Main kernel: grid (64 i-tiles, 64 j-tiles), 256 threads.
// Load phase: stage token list + warp-transposed W tile (+bias) into smT[i][j],
//   fused exp() column-partial accumulation (each W element exp'd once).
// Token phase: ONE cp.async.bulk (512B smem->gmem TMA store) per token,
//   issued one-token-per-thread — no register traffic, no warp-wide LSU dance.
__global__ __launch_bounds__(256, 3)
void k_main(const float* __restrict__ W, const float* __restrict__ bias,
            float* __restrict__ out) {
    __shared__ __align__(16) float smT[TI * SMSTRIDE];  // [128][132] transposed
    __shared__ float sbias[TJ];
    __shared__ float psum[8][32];
    __shared__ int   slist[LCAP];

    const int i0   = blockIdx.x * TI;
    const int j0   = blockIdx.y * TJ;
    const int tid  = threadIdx.x;
    const int lane = tid & 31;
    const int wid  = tid >> 5;
    const int bi   = blockIdx.x;
    const int base = bi * SEGCAP;
    const int cnt  = g_cnt[bi];

    // Stage token list (coalesced, overlaps with W loads below).
    const int scnt = cnt < LCAP ? cnt : LCAP;
    for (int k = tid; k < scnt; k += 256) slist[k] = g_list[base + k];

    if (tid < TJ) sbias[tid] = bias[j0 + tid];
    __syncthreads();   // sbias ready (W-load needs it)

    // Each warp owns i-group (wid&3) and j-groups {wid>>2, (wid>>2)+2}.
    const int ii0 = (wid & 3) * 32;
    float acc = 0.0f;

#pragma unroll
    for (int s = 0; s < 2; s++) {
        const int jj0 = ((wid >> 2) + 2 * s) * 32;
        float v[32];
#pragma unroll
        for (int r = 0; r < 32; r++)
            v[r] = __ldcs(&W[(size_t)(j0 + jj0 + r) * VOCAB + i0 + ii0 + lane]);
#pragma unroll
        for (int r = 0; r < 32; r++) {
            v[r] += sbias[jj0 + r];
            acc += __expf(v[r]);
        }
        float* row = &smT[(ii0 + lane) * SMSTRIDE + jj0];
#pragma unroll
        for (int c = 0; c < 8; c++)
            reinterpret_cast<float4*>(row)[c] =
                make_float4(v[4 * c], v[4 * c + 1], v[4 * c + 2], v[4 * c + 3]);
    }
    psum[wid][lane] = acc;
    __syncthreads();

    // Column exp-partials -> global (no atomics).
    if (tid < TI) {
        int g = tid >> 5, l = tid & 31;
        g_partial[(size_t)blockIdx.y * VOCAB + i0 + tid] =
            psum[g][l] + psum[g + 4][l];
    }

    // Make generic-proxy STS data visible to the async (TMA) proxy.
    asm volatile("fence.proxy.async.shared::cta;" ::: "memory");

    // Token phase: one 512B TMA bulk store per token, one token per thread.
    // Commit/wait every 64 per-thread ops to bound async-queue depth.
    const uint32_t smT_u32 = (uint32_t)__cvta_generic_to_shared(smT);
    int inflight = 0;
    for (int k = tid; k < cnt; k += 256) {
        int e  = (k < LCAP) ? slist[k] : g_list[base + k];
        int t  = e & 0xFFFF;
        int di = (e >> 16) - i0;
        uint32_t saddr = smT_u32 + (uint32_t)di * (SMSTRIDE * 4);
        const float* gptr = out + (size_t)t * VOCAB + j0;
        asm volatile(
            "cp.async.bulk.global.shared::cta.bulk_group [%0], [%1], %2;"
            :: "l"(gptr), "r"(saddr), "r"(512) : "memory");
        if (++inflight == 64) {
            asm volatile("cp.async.bulk.commit_group;" ::: "memory");
            asm volatile("cp.async.bulk.wait_group 0;" ::: "memory");
            inflight = 0;
        }
    }
    asm volatile("cp.async.bulk.commit_group;" ::: "memory");
    asm volatile("cp.async.bulk.wait_group 0;" ::: "memory");
}

// ---------------------------------------------------------------------------
__global__ void k_sumS() {
    int i = blockIdx.x * blockDim.x + threadIdx.x;
    float s = 0.0f;
#pragma unroll 8
    for (int jb = 0; jb < NJB; jb++)
        s += g_partial[(size_t)jb * VOCAB + i];
    g_S[i] = s;
}

__global__ void k_nll(const int* __restrict__ idx, const int* __restrict__ tgt,
                      const float* __restrict__ W, const float* __restrict__ bias) {
    int t = blockIdx.x * blockDim.x + threadIdx.x;
    if (t < NTOK) {
        int tg = tgt[t];
        float nll = 0.0f;
        if (tg >= 0) {
            float lt = W[(size_t)tg * VOCAB + idx[t]] + bias[tg];
            nll = logf(g_S[idx[t]]) - lt;
        }
        g_nll[t] = nll;
    }
}

__global__ void k_reduce(const int* __restrict__ tgt, float* __restrict__ out,
                         int loss_index) {
    __shared__ float ssum[256];
    __shared__ float scnt[256];
    int tid = threadIdx.x;
    float s = 0.0f, c = 0.0f;
    for (int t = tid; t < NTOK; t += 256) {
        s += g_nll[t];
        c += (tgt[t] != -1) ? 1.0f : 0.0f;
    }
    ssum[tid] = s; scnt[tid] = c;
    __syncthreads();
    for (int o = 128; o > 0; o >>= 1) {
        if (tid < o) { ssum[tid] += ssum[tid + o]; scnt[tid] += scnt[tid + o]; }
        __syncthreads();
    }
    if (tid == 0) out[loss_index] = ssum[0] / fmaxf(scnt[0], 1.0f);
    // Reset bin counters for the next graph replay.
    if (tid < NIB) g_cnt[tid] = 0;
}

// ---------------------------------------------------------------------------
extern "C" void kernel_launch(void* const* d_in, const int* in_sizes, int n_in,
                              void* d_out, int out_size) {
    const int*   idx  = (const int*)d_in[0];
    const int*   tgt  = (const int*)d_in[1];
    const float* W    = (const float*)d_in[2];
    const float* bias = (const float*)d_in[3];
    float*       out  = (float*)d_out;

    k_scatter<<<NTOK / 256, 256>>>(idx);             // launch 1
    k_pad<<<1, 32>>>();                              // launch 2
    k_pad<<<1, 32>>>();                              // launch 3
    k_main<<<dim3(NIB, NJB), 256>>>(W, bias, out);   // launch 4 -> ncu target
    k_sumS<<<VOCAB / 256, 256>>>();
    k_nll<<<NTOK / 256, 256>>>(idx, tgt, W, bias);
    k_reduce<<<1, 256>>>(tgt, out, out_size - 1);
}

// round 9
// speedup vs baseline: 1.5812x; 1.0539x over previous
#include <cuda_runtime.h>
#include <cstdint>

// Problem constants
#define VOCAB  8192
#define NTOK   16384          // B*T = 8*2048
#define TI     128            // vocab columns per i-tile (64 tiles)
#define TJ     64             // output j per block tile  (128 tiles)
#define NIB    (VOCAB / TI)   // 64 i-tiles (= segment bins)
#define NJB    (VOCAB / TJ)   // 128 j-blocks
#define SEGCAP NTOK           // worst-case tokens per bin (adversarial-safe)
#define LCAP   1024           // smem-staged list capacity (mean 256, sigma 16)
#define SMSTRIDE 68           // smT row stride in floats: 272B (16B mult, cf banks)

// Scratch (__device__ globals — zero-initialized at module load; no allocation)
__device__ int   g_cnt[NIB];                 // per-bin token counts
__device__ int   g_list[NIB * SEGCAP];       // packed (vocab << 16) | token
__device__ float g_partial[NJB * VOCAB];     // per-jblock column partials of sum(exp)
__device__ float g_S[VOCAB];                 // S[i] = sum_j exp(W[j,i]+b[j])
__device__ float g_loss[2];                  // {sum_nll, count}
__device__ int   g_done;                     // finished-block counter

// ---------------------------------------------------------------------------
// Scatter tokens into per-i-tile segments (smem-aggregated atomics).
__global__ __launch_bounds__(256)
void k_scatter(const int* __restrict__ idx) {
    __shared__ int lcnt[NIB];
    __shared__ int lbase[NIB];
    int tid = threadIdx.x;
    if (tid < NIB) lcnt[tid] = 0;
    __syncthreads();
    int t = blockIdx.x * 256 + tid;
    int v = idx[t];
    int bin = v >> 7;
    int lp = atomicAdd(&lcnt[bin], 1);
    __syncthreads();
    if (tid < NIB && lcnt[tid] > 0)
        lbase[tid] = atomicAdd(&g_cnt[tid], lcnt[tid]);
    __syncthreads();
    g_list[bin * SEGCAP + lbase[bin] + lp] = (v << 16) | t;
}

// ---------------------------------------------------------------------------
// Main kernel: grid (64 i-tiles, 128 j-tiles), 256 threads, 4 CTAs/SM.
// Load phase: stage token list + warp-transposed W tile (+bias) into smT[i][j],
//   fused exp() column-partial accumulation (each W element exp'd once).
// Token phase: ONE cp.async.bulk (256B smem->gmem TMA store) per token/thread.
__global__ __launch_bounds__(256, 4)
void k_main(const float* __restrict__ W, const float* __restrict__ bias,
            float* __restrict__ out) {
    __shared__ __align__(16) float smT[TI * SMSTRIDE];  // [128][68] transposed
    __shared__ float sbias[TJ];
    __shared__ float psum[8][32];
    __shared__ int   slist[LCAP];

    const int i0   = blockIdx.x * TI;
    const int j0   = blockIdx.y * TJ;
    const int tid  = threadIdx.x;
    const int lane = tid & 31;
    const int wid  = tid >> 5;
    const int bi   = blockIdx.x;
    const int base = bi * SEGCAP;
    const int cnt  = g_cnt[bi];

    // Stage token list (coalesced, overlaps with W loads below).
    const int scnt = cnt < LCAP ? cnt : LCAP;
    for (int k = tid; k < scnt; k += 256) slist[k] = g_list[base + k];

    if (tid < TJ) sbias[tid] = bias[j0 + tid];
    __syncthreads();   // sbias ready (W-load needs it)

    // Warp (ig = wid&3, jg = wid>>2) owns the 32i x 32j subtile
    // (i0+ig*32 .., j0+jg*32 ..), processed as two 16-j chunks (reg pressure).
    const int ii0 = (wid & 3) * 32;
    const int jj0 = (wid >> 2) * 32;
    float acc = 0.0f;

#pragma unroll
    for (int s = 0; s < 2; s++) {
        const int jb = jj0 + s * 16;
        float v[16];
#pragma unroll
        for (int r = 0; r < 16; r++)
            v[r] = __ldcs(&W[(size_t)(j0 + jb + r) * VOCAB + i0 + ii0 + lane]);
#pragma unroll
        for (int r = 0; r < 16; r++) {
            v[r] += sbias[jb + r];
            acc += __expf(v[r]);
        }
        float* row = &smT[(ii0 + lane) * SMSTRIDE + jb];
#pragma unroll
        for (int c = 0; c < 4; c++)
            reinterpret_cast<float4*>(row)[c] =
                make_float4(v[4 * c], v[4 * c + 1], v[4 * c + 2], v[4 * c + 3]);
    }
    psum[wid][lane] = acc;
    __syncthreads();

    // Column exp-partials -> global (no atomics).
    if (tid < TI) {
        int g = tid >> 5, l = tid & 31;
        g_partial[(size_t)blockIdx.y * VOCAB + i0 + tid] =
            psum[g][l] + psum[g + 4][l];
    }

    // Make generic-proxy STS data visible to the async (TMA) proxy.
    asm volatile("fence.proxy.async.shared::cta;" ::: "memory");

    // Token phase: one 256B TMA bulk store per token, one token per thread.
    const uint32_t smT_u32 = (uint32_t)__cvta_generic_to_shared(smT);
    int inflight = 0;
    for (int k = tid; k < cnt; k += 256) {
        int e  = (k < LCAP) ? slist[k] : g_list[base + k];
        int t  = e & 0xFFFF;
        int di = (e >> 16) - i0;
        uint32_t saddr = smT_u32 + (uint32_t)di * (SMSTRIDE * 4);
        const float* gptr = out + (size_t)t * VOCAB + j0;
        asm volatile(
            "cp.async.bulk.global.shared::cta.bulk_group [%0], [%1], %2;"
            :: "l"(gptr), "r"(saddr), "r"(TJ * 4) : "memory");
        if (++inflight == 64) {
            asm volatile("cp.async.bulk.commit_group;" ::: "memory");
            asm volatile("cp.async.bulk.wait_group 0;" ::: "memory");
            inflight = 0;
        }
    }
    asm volatile("cp.async.bulk.commit_group;" ::: "memory");
    asm volatile("cp.async.bulk.wait_group 0;" ::: "memory");
}

// ---------------------------------------------------------------------------
__global__ void k_sumS() {
    int i = blockIdx.x * blockDim.x + threadIdx.x;
    float s = 0.0f;
#pragma unroll 8
    for (int jb = 0; jb < NJB; jb++)
        s += g_partial[(size_t)jb * VOCAB + i];
    g_S[i] = s;
}

// Fused NLL + mean-reduction + per-replay state reset (last-block finalize).
__global__ __launch_bounds__(256)
void k_nllred(const int* __restrict__ idx, const int* __restrict__ tgt,
              const float* __restrict__ W, const float* __restrict__ bias,
              float* __restrict__ out, int loss_index) {
    __shared__ float ssum[256];
    __shared__ float scnt[256];
    int tid = threadIdx.x;
    int t = blockIdx.x * 256 + tid;
    float nll = 0.0f, c = 0.0f;
    int tg = tgt[t];
    if (tg >= 0) {
        float lt = W[(size_t)tg * VOCAB + idx[t]] + bias[tg];
        nll = logf(g_S[idx[t]]) - lt;
        c = 1.0f;
    }
    ssum[tid] = nll; scnt[tid] = c;
    __syncthreads();
    for (int o = 128; o > 0; o >>= 1) {
        if (tid < o) { ssum[tid] += ssum[tid + o]; scnt[tid] += scnt[tid + o]; }
        __syncthreads();
    }
    if (tid == 0) {
        atomicAdd(&g_loss[0], ssum[0]);
        atomicAdd(&g_loss[1], scnt[0]);
        __threadfence();
        int d = atomicAdd(&g_done, 1);
        if (d == (NTOK / 256) - 1) {         // last block: finalize + reset
            out[loss_index] = g_loss[0] / fmaxf(g_loss[1], 1.0f);
            g_loss[0] = 0.0f; g_loss[1] = 0.0f; g_done = 0;
            for (int i = 0; i < NIB; i++) g_cnt[i] = 0;
        }
    }
}

// ---------------------------------------------------------------------------
extern "C" void kernel_launch(void* const* d_in, const int* in_sizes, int n_in,
                              void* d_out, int out_size) {
    const int*   idx  = (const int*)d_in[0];
    const int*   tgt  = (const int*)d_in[1];
    const float* W    = (const float*)d_in[2];
    const float* bias = (const float*)d_in[3];
    float*       out  = (float*)d_out;

    k_scatter<<<NTOK / 256, 256>>>(idx);
    k_main<<<dim3(NIB, NJB), 256>>>(W, bias, out);
    k_sumS<<<VOCAB / 256, 256>>>();
    k_nllred<<<NTOK / 256, 256>>>(idx, tgt, W, bias, out, out_size - 1);
}

// round 10
// speedup vs baseline: 1.6522x; 1.0449x over previous
#include <cuda_runtime.h>
#include <cstdint>

// Problem constants
#define VOCAB  8192
#define NTOK   16384          // B*T = 8*2048
#define TI     128            // vocab columns per i-tile (64 tiles)
#define TJ     64             // output j per block tile  (128 tiles)
#define NIB    (VOCAB / TI)   // 64 i-tiles (= segment bins)
#define NJB    (VOCAB / TJ)   // 128 j-blocks
#define SEGCAP NTOK           // worst-case tokens per bin (adversarial-safe)
#define SMSTRIDE 68           // smT row stride in floats: 272B (16B mult, cf banks)
#define NLLB   128            // blocks in fused loss kernel (<= #SM, co-resident)

// Scratch (__device__ globals — zero-initialized at module load; no allocation)
__device__ int   g_cnt[NIB];                 // per-bin token counts
__device__ int2  g_list[NIB * SEGCAP];       // {(vocab<<16)|token, target}
__device__ float g_partial[NJB * VOCAB];     // per-jblock column partials of sum(exp)
__device__ float g_S[VOCAB];                 // S[i] = sum_j exp(W[j,i]+b[j])
__device__ float g_logit[NTOK];              // gathered W[tgt,idx]+b[tgt] (from k_main)
__device__ float g_loss[2];                  // {sum_nll, count}
__device__ int   g_sync;                     // grid-sync counter (fused loss kernel)
__device__ int   g_done;                     // finished-block counter (finalize)

// ---------------------------------------------------------------------------
// Scatter tokens into per-i-tile segments (smem-aggregated atomics).
__global__ __launch_bounds__(256)
void k_scatter(const int* __restrict__ idx, const int* __restrict__ tgt) {
    __shared__ int lcnt[NIB];
    __shared__ int lbase[NIB];
    int tid = threadIdx.x;
    if (tid < NIB) lcnt[tid] = 0;
    __syncthreads();
    int t = blockIdx.x * 256 + tid;
    int v = idx[t];
    int tg = tgt[t];
    int bin = v >> 7;
    int lp = atomicAdd(&lcnt[bin], 1);
    __syncthreads();
    if (tid < NIB && lcnt[tid] > 0)
        lbase[tid] = atomicAdd(&g_cnt[tid], lcnt[tid]);
    __syncthreads();
    g_list[bin * SEGCAP + lbase[bin] + lp] = make_int2((v << 16) | t, tg);
}

// ---------------------------------------------------------------------------
// Main kernel: grid (64 i-tiles, 128 j-tiles), 256 threads, 4 CTAs/SM.
// Load phase: warp-transposed W tile (+bias) into smT[i][j], fused exp()
//   column-partial accumulation; token int2 preloaded under the tile load.
// Token phase: ONE cp.async.bulk (256B smem->gmem TMA store) per token/thread,
//   plus predicated 1-float target-logit gather into g_logit.
__global__ __launch_bounds__(256, 4)
void k_main(const float* __restrict__ W, const float* __restrict__ bias,
            float* __restrict__ out) {
    __shared__ __align__(16) float smT[TI * SMSTRIDE];  // [128][68] transposed
    __shared__ float sbias[TJ];
    __shared__ float psum[8][32];

    const int i0   = blockIdx.x * TI;
    const int j0   = blockIdx.y * TJ;
    const int tid  = threadIdx.x;
    const int lane = tid & 31;
    const int wid  = tid >> 5;
    const int bi   = blockIdx.x;
    const int base = bi * SEGCAP;
    const int cnt  = g_cnt[bi];

    // Preload this thread's first token entry (latency hidden under W loads).
    int2 e0 = make_int2(0, -1);
    if (tid < cnt) e0 = g_list[base + tid];

    if (tid < TJ) sbias[tid] = bias[j0 + tid];
    __syncthreads();   // sbias ready (W-load needs it)

    // Warp (ig = wid&3, jg = wid>>2) owns the 32i x 32j subtile,
    // processed as two 16-j chunks (register pressure).
    const int ii0 = (wid & 3) * 32;
    const int jj0 = (wid >> 2) * 32;
    float acc = 0.0f;

#pragma unroll
    for (int s = 0; s < 2; s++) {
        const int jb = jj0 + s * 16;
        float v[16];
#pragma unroll
        for (int r = 0; r < 16; r++)
            v[r] = __ldcs(&W[(size_t)(j0 + jb + r) * VOCAB + i0 + ii0 + lane]);
#pragma unroll
        for (int r = 0; r < 16; r++) {
            v[r] += sbias[jb + r];
            acc += __expf(v[r]);
        }
        float* row = &smT[(ii0 + lane) * SMSTRIDE + jb];
#pragma unroll
        for (int c = 0; c < 4; c++)
            reinterpret_cast<float4*>(row)[c] =
                make_float4(v[4 * c], v[4 * c + 1], v[4 * c + 2], v[4 * c + 3]);
    }
    psum[wid][lane] = acc;
    __syncthreads();

    // Column exp-partials -> global (no atomics).
    if (tid < TI) {
        int g = tid >> 5, l = tid & 31;
        g_partial[(size_t)blockIdx.y * VOCAB + i0 + tid] =
            psum[g][l] + psum[g + 4][l];
    }

    // Make generic-proxy STS data visible to the async (TMA) proxy.
    asm volatile("fence.proxy.async.shared::cta;" ::: "memory");

    // Token phase: one 256B TMA bulk store per token, one token per thread.
    const uint32_t smT_u32 = (uint32_t)__cvta_generic_to_shared(smT);
    for (int k = tid; k < cnt; k += 256) {
        int2 e = (k == tid) ? e0 : g_list[base + k];
        int t  = e.x & 0xFFFF;
        int di = (e.x >> 16) - i0;
        uint32_t saddr = smT_u32 + (uint32_t)di * (SMSTRIDE * 4);
        const float* gptr = out + (size_t)t * VOCAB + j0;
        asm volatile(
            "cp.async.bulk.global.shared::cta.bulk_group [%0], [%1], %2;"
            :: "l"(gptr), "r"(saddr), "r"(TJ * 4) : "memory");
        // Target-logit gather: this tile holds W[tg, idx[t]]+b iff tg in j-range.
        unsigned dj = (unsigned)(e.y - j0);
        if (dj < TJ)
            g_logit[t] = smT[di * SMSTRIDE + dj];
    }
    asm volatile("cp.async.bulk.commit_group;" ::: "memory");
    asm volatile("cp.async.bulk.wait_group 0;" ::: "memory");
}

// ---------------------------------------------------------------------------
// Fused: S-reduction (phase 1) -> grid sync -> NLL + mean (phase 2).
// NLLB=128 blocks of 128 threads: <= #SM, all co-resident -> sync is safe.
__global__ __launch_bounds__(128)
void k_snll(const int* __restrict__ idx, const int* __restrict__ tgt,
            float* __restrict__ out, int loss_index) {
    __shared__ float sh[64];
    __shared__ float ssum[128];
    __shared__ float scnt[128];
    const int tid = threadIdx.x;
    const int b   = blockIdx.x;

    // Phase 1: S[i] for i in [b*64, b*64+64); 2 threads per i.
    {
        int il = tid & 63, half = tid >> 6;
        int i = b * 64 + il;
        float s = 0.0f;
        for (int jb = half; jb < NJB; jb += 2)
            s += g_partial[(size_t)jb * VOCAB + i];
        if (half == 0) sh[il] = s;
        __syncthreads();
        if (half == 1) g_S[i] = s + sh[il];
    }
    __threadfence();
    __syncthreads();
    if (tid == 0) {
        atomicAdd(&g_sync, 1);
        while (atomicAdd(&g_sync, 0) < NLLB) __nanosleep(64);
    }
    __syncthreads();
    __threadfence();   // acquire: g_S writes from all blocks now visible

    // Phase 2: per-token NLL from g_logit (bias included) + g_S gather.
    {
        int t = b * 128 + tid;
        int tg = tgt[t];
        float nll = 0.0f, c = 0.0f;
        if (tg >= 0) {
            nll = logf(g_S[idx[t]]) - g_logit[t];
            c = 1.0f;
        }
        ssum[tid] = nll; scnt[tid] = c;
    }
    __syncthreads();
    for (int o = 64; o > 0; o >>= 1) {
        if (tid < o) { ssum[tid] += ssum[tid + o]; scnt[tid] += scnt[tid + o]; }
        __syncthreads();
    }
    if (tid == 0) {
        atomicAdd(&g_loss[0], ssum[0]);
        atomicAdd(&g_loss[1], scnt[0]);
        __threadfence();
        int d = atomicAdd(&g_done, 1);
        if (d == NLLB - 1) {   // last block: finalize + reset for next replay
            out[loss_index] = g_loss[0] / fmaxf(g_loss[1], 1.0f);
            g_loss[0] = 0.0f; g_loss[1] = 0.0f;
            g_done = 0; g_sync = 0;
            for (int i = 0; i < NIB; i++) g_cnt[i] = 0;
        }
    }
}

// ---------------------------------------------------------------------------
extern "C" void kernel_launch(void* const* d_in, const int* in_sizes, int n_in,
                              void* d_out, int out_size) {
    const int*   idx  = (const int*)d_in[0];
    const int*   tgt  = (const int*)d_in[1];
    const float* W    = (const float*)d_in[2];
    const float* bias = (const float*)d_in[3];
    float*       out  = (float*)d_out;

    k_scatter<<<NTOK / 256, 256>>>(idx, tgt);
    k_main<<<dim3(NIB, NJB), 256>>>(W, bias, out);
    k_snll<<<NLLB, 128>>>(idx, tgt, out, out_size - 1);
}

// round 11
// speedup vs baseline: 1.6529x; 1.0004x over previous
#include <cuda_runtime.h>
#include <cstdint>

// Problem constants
#define VOCAB  8192
#define NTOK   16384          // B*T = 8*2048
#define TI     128            // vocab columns per i-tile (64 tiles)
#define TJ     64             // output j per block tile  (128 tiles)
#define NIB    (VOCAB / TI)   // 64 i-tiles (= segment bins)
#define NJB    (VOCAB / TJ)   // 128 j-blocks
#define SEGCAP NTOK           // worst-case tokens per bin (adversarial-safe)
#define SMSTRIDE 68           // smT row stride in floats: 272B (16B mult, cf banks)
#define NLLB   128            // blocks in loss kernel

// Scratch (__device__ globals — zero-initialized at module load; no allocation)
__device__ int   g_cnt[NIB];                 // per-bin token counts
__device__ int2  g_list[NIB * SEGCAP];       // {(vocab<<16)|token, target}
__device__ float g_S[VOCAB];                 // S[i] = sum_j exp(W[j,i]+b[j]) (atomic)
__device__ float g_logit[NTOK];              // gathered W[tgt,idx]+b[tgt] (from k_main)
__device__ float g_loss[2];                  // {sum_nll, count}
__device__ int   g_ready;                    // scatter-complete counter (0..NIB)
__device__ int   g_done;                     // finished-block counter (finalize)

// ---------------------------------------------------------------------------
// Main kernel: grid (64 i-tiles, 128 j-tiles), 256 threads, 4 CTAs/SM.
// Blocks with blockIdx.y==0 (linear bids 0..63 -> wave 1) first scatter their
//   256-token slice into per-bin segments, then proceed as normal tiles.
// Load phase (ungated): warp-transposed W tile (+bias) into smT[i][j], fused
//   exp() column partials -> float atomicAdd into g_S (no partial buffer).
// Token phase (gated on scatter completion): one cp.async.bulk 256B TMA store
//   per token per thread + predicated target-logit gather into g_logit.
__global__ __launch_bounds__(256, 4)
void k_main(const int* __restrict__ idx, const int* __restrict__ tgt,
            const float* __restrict__ W, const float* __restrict__ bias,
            float* __restrict__ out) {
    __shared__ __align__(16) float smT[TI * SMSTRIDE];  // [128][68] transposed
    __shared__ float sbias[TJ];
    __shared__ float psum[8][32];
    __shared__ int   lcnt[NIB];
    __shared__ int   lbase[NIB];

    const int i0   = blockIdx.x * TI;
    const int j0   = blockIdx.y * TJ;
    const int tid  = threadIdx.x;
    const int lane = tid & 31;
    const int wid  = tid >> 5;
    const int bi   = blockIdx.x;
    const int base = bi * SEGCAP;

    // ---- Fused scatter (first 64 linear bids only; wave-1 resident) ----
    if (blockIdx.y == 0) {
        if (tid < NIB) lcnt[tid] = 0;
        __syncthreads();
        int t  = bi * 256 + tid;
        int v  = idx[t];
        int tg = tgt[t];
        int bin = v >> 7;
        int lp = atomicAdd(&lcnt[bin], 1);
        __syncthreads();
        if (tid < NIB && lcnt[tid] > 0)
            lbase[tid] = atomicAdd(&g_cnt[tid], lcnt[tid]);
        __syncthreads();
        g_list[bin * SEGCAP + lbase[bin] + lp] = make_int2((v << 16) | t, tg);
        __syncthreads();
        __threadfence();                       // release g_list/g_cnt writes
        if (tid == 0) atomicAdd(&g_ready, 1);
    }

    if (tid < TJ) sbias[tid] = bias[j0 + tid];
    __syncthreads();   // sbias ready (W-load needs it)

    // ---- Load phase: warp (ig=wid&3, jg=wid>>2) owns a 32i x 32j subtile ----
    const int ii0 = (wid & 3) * 32;
    const int jj0 = (wid >> 2) * 32;
    float acc = 0.0f;

#pragma unroll
    for (int s = 0; s < 2; s++) {
        const int jb = jj0 + s * 16;
        float v[16];
#pragma unroll
        for (int r = 0; r < 16; r++)
            v[r] = __ldcs(&W[(size_t)(j0 + jb + r) * VOCAB + i0 + ii0 + lane]);
#pragma unroll
        for (int r = 0; r < 16; r++) {
            v[r] += sbias[jb + r];
            acc += __expf(v[r]);
        }
        float* row = &smT[(ii0 + lane) * SMSTRIDE + jb];
#pragma unroll
        for (int c = 0; c < 4; c++)
            reinterpret_cast<float4*>(row)[c] =
                make_float4(v[4 * c], v[4 * c + 1], v[4 * c + 2], v[4 * c + 3]);
    }
    psum[wid][lane] = acc;
    __syncthreads();

    // Column exp-partials -> g_S via spread-address float atomics (REDG).
    if (tid < TI) {
        int g = tid >> 5, l = tid & 31;
        atomicAdd(&g_S[i0 + tid], psum[g][l] + psum[g + 4][l]);
    }

    // Make generic-proxy STS data visible to the async (TMA) proxy.
    asm volatile("fence.proxy.async.shared::cta;" ::: "memory");

    // ---- Gate token phase on scatter completion (acquire) ----
    if (tid == 0) {
        while (atomicAdd(&g_ready, 0) < NIB) __nanosleep(32);
    }
    __syncthreads();
    __threadfence();

    const int cnt = g_cnt[bi];

    // ---- Token phase: one 256B TMA bulk store per token per thread ----
    const uint32_t smT_u32 = (uint32_t)__cvta_generic_to_shared(smT);
    for (int k = tid; k < cnt; k += 256) {
        int2 e = g_list[base + k];
        int t  = e.x & 0xFFFF;
        int di = (e.x >> 16) - i0;
        uint32_t saddr = smT_u32 + (uint32_t)di * (SMSTRIDE * 4);
        const float* gptr = out + (size_t)t * VOCAB + j0;
        asm volatile(
            "cp.async.bulk.global.shared::cta.bulk_group [%0], [%1], %2;"
            :: "l"(gptr), "r"(saddr), "r"(TJ * 4) : "memory");
        // Target-logit gather: this tile holds W[tg, idx[t]]+b iff tg in j-range.
        unsigned dj = (unsigned)(e.y - j0);
        if (dj < TJ)
            g_logit[t] = smT[di * SMSTRIDE + dj];
    }
    asm volatile("cp.async.bulk.commit_group;" ::: "memory");
    asm volatile("cp.async.bulk.wait_group 0;" ::: "memory");
}

// ---------------------------------------------------------------------------
// Loss kernel: per-token NLL from g_logit + L2-hot g_S, block reduce,
// last-block finalize (writes loss, resets all per-replay state).
__global__ __launch_bounds__(128)
void k_snll(const int* __restrict__ idx, const int* __restrict__ tgt,
            float* __restrict__ out, int loss_index) {
    __shared__ float ssum[128];
    __shared__ float scnt[128];
    const int tid = threadIdx.x;
    const int t   = blockIdx.x * 128 + tid;

    int tg = tgt[t];
    float nll = 0.0f, c = 0.0f;
    if (tg >= 0) {
        nll = logf(g_S[idx[t]]) - g_logit[t];
        c = 1.0f;
    }
    ssum[tid] = nll; scnt[tid] = c;
    __syncthreads();
    for (int o = 64; o > 0; o >>= 1) {
        if (tid < o) { ssum[tid] += ssum[tid + o]; scnt[tid] += scnt[tid + o]; }
        __syncthreads();
    }
    if (tid == 0) {
        atomicAdd(&g_loss[0], ssum[0]);
        atomicAdd(&g_loss[1], scnt[0]);
        __threadfence();
        int d = atomicAdd(&g_done, 1);
        if (d == NLLB - 1) ssum[0] = -1.0f;   // mark finalizer
    }
    __syncthreads();
    // Finalizer block: write loss + reset all per-replay state.
    if (ssum[0] == -1.0f) {
        if (tid == 0) {
            out[loss_index] = g_loss[0] / fmaxf(g_loss[1], 1.0f);
            g_loss[0] = 0.0f; g_loss[1] = 0.0f;
            g_done = 0; g_ready = 0;
        }
        if (tid < NIB) g_cnt[tid] = 0;
        for (int i = tid; i < VOCAB; i += 128) g_S[i] = 0.0f;
    }
}

// ---------------------------------------------------------------------------
extern "C" void kernel_launch(void* const* d_in, const int* in_sizes, int n_in,
                              void* d_out, int out_size) {
    const int*   idx  = (const int*)d_in[0];
    const int*   tgt  = (const int*)d_in[1];
    const float* W    = (const float*)d_in[2];
    const float* bias = (const float*)d_in[3];
    float*       out  = (float*)d_out;

    k_main<<<dim3(NIB, NJB), 256>>>(idx, tgt, W, bias, out);
    k_snll<<<NLLB, 128>>>(idx, tgt, out, out_size - 1);
}